// round 14
// baseline (speedup 1.0000x reference)
#include <cuda_runtime.h>
#include <cstdint>
#include <math.h>

#define Bdim 16
#define Tdim 2048
#define Ddim 512
#define Hdim 512

// ---------------- helpers --------------------------------------------------
__device__ __forceinline__ unsigned long long pk2(float x, float y) {
    unsigned long long r;
    asm("mov.b64 %0, {%1,%2};" : "=l"(r) : "f"(x), "f"(y));
    return r;
}
__device__ __forceinline__ void fma2(unsigned long long& d, unsigned long long a, unsigned long long b) {
    asm("fma.rn.f32x2 %0, %1, %2, %0;" : "+l"(d) : "l"(a), "l"(b));
}
__device__ __forceinline__ void add2(unsigned long long& d, unsigned long long a) {
    asm("add.rn.f32x2 %0, %0, %1;" : "+l"(d) : "l"(a));
}
__device__ __forceinline__ float2 upk2(unsigned long long v) {
    float2 f;
    asm("mov.b64 {%0,%1}, %2;" : "=f"(f.x), "=f"(f.y) : "l"(v));
    return f;
}
__device__ __forceinline__ float ldcg_f1(const float* p) {
    float v;
    asm volatile("ld.global.cg.f32 %0, [%1];" : "=f"(v) : "l"(p));
    return v;
}
__device__ __forceinline__ void stcg_f4(void* p, float4 v) {
    asm volatile("st.global.cg.v4.f32 [%0], {%1,%2,%3,%4};"
                 :: "l"(p), "f"(v.x), "f"(v.y), "f"(v.z), "f"(v.w) : "memory");
}
__device__ __forceinline__ uint32_t s2u(const void* p) {
    uint32_t a;
    asm("{ .reg .u64 t; cvta.to.shared.u64 t, %1; cvt.u32.u64 %0, t; }" : "=r"(a) : "l"(p));
    return a;
}

// ---------------- Phase 1: pre = x @ W_xh + b  (fp32 SGEMM, f32x2) --------
// Writes straight into d_out (in-place pre buffer; the RNN kernel overwrites
// each element after consuming it). No global sync state needed this round.
#define GTM 128
#define GTN 128
#define GTK 16

__global__ void __launch_bounds__(256, 2)
gemm_pre_kernel(const float* __restrict__ X, const float* __restrict__ W,
                const float* __restrict__ bias, float* __restrict__ out) {
    __shared__ __align__(16) float As[2][GTK][GTM];
    __shared__ __align__(16) float Bs[2][GTK][GTN];

    const int tid = threadIdx.x;
    const int mb = blockIdx.x * GTM;
    const int nb = blockIdx.y * GTN;
    const int K = Ddim, N = Hdim;

    unsigned long long acc[8][4];
#pragma unroll
    for (int i = 0; i < 8; i++)
#pragma unroll
        for (int q = 0; q < 4; q++) acc[i][q] = 0ull;

    const int tm = (tid >> 4) << 3;
    const int tn = (tid & 15) << 3;

    auto loadA = [&](int kt, int buf) {
#pragma unroll
        for (int i = 0; i < 2; i++) {
            int idx = tid + i * 256;
            int row = idx >> 2;
            int kq  = (idx & 3) << 2;
            float4 v = *(const float4*)(X + (size_t)(mb + row) * K + kt * GTK + kq);
            As[buf][kq + 0][row] = v.x;
            As[buf][kq + 1][row] = v.y;
            As[buf][kq + 2][row] = v.z;
            As[buf][kq + 3][row] = v.w;
        }
    };
    auto loadB = [&](int kt, int buf) {
#pragma unroll
        for (int i = 0; i < 2; i++) {
            int idx = tid + i * 256;
            int kk = idx >> 5;
            int nq = (idx & 31) << 2;
            *(float4*)(&Bs[buf][kk][nq]) =
                *(const float4*)(W + (size_t)(kt * GTK + kk) * N + nb + nq);
        }
    };

    loadA(0, 0);
    loadB(0, 0);
    __syncthreads();

    const int NT = K / GTK;
    for (int kt = 0; kt < NT; ++kt) {
        const int cur = kt & 1;
        if (kt + 1 < NT) {
            loadA(kt + 1, cur ^ 1);
            loadB(kt + 1, cur ^ 1);
        }
#pragma unroll
        for (int kk = 0; kk < GTK; ++kk) {
            float4 A0 = *(const float4*)(&As[cur][kk][tm]);
            float4 A1 = *(const float4*)(&As[cur][kk][tm + 4]);
            ulonglong2 B0 = *(const ulonglong2*)(&Bs[cur][kk][tn]);
            ulonglong2 B1 = *(const ulonglong2*)(&Bs[cur][kk][tn + 4]);
            float av[8] = {A0.x, A0.y, A0.z, A0.w, A1.x, A1.y, A1.z, A1.w};
#pragma unroll
            for (int mi = 0; mi < 8; ++mi) {
                unsigned long long ai = pk2(av[mi], av[mi]);
                fma2(acc[mi][0], ai, B0.x);
                fma2(acc[mi][1], ai, B0.y);
                fma2(acc[mi][2], ai, B1.x);
                fma2(acc[mi][3], ai, B1.y);
            }
        }
        __syncthreads();
    }

    unsigned long long bz[4];
#pragma unroll
    for (int q = 0; q < 4; q++)
        bz[q] = pk2(bias[nb + tn + 2 * q], bias[nb + tn + 2 * q + 1]);
#pragma unroll
    for (int mi = 0; mi < 8; ++mi) {
#pragma unroll
        for (int q = 0; q < 4; q++) {
            add2(acc[mi][q], bz[q]);
            *(unsigned long long*)(out + (size_t)(mb + tm + mi) * N + nb + tn + 2 * q) =
                acc[mi][q];
        }
    }
}

// ---------------- Phase 2: sequential tanh RNN (DSMEM + HW mbarrier) -------
// 16 clusters (one per batch) x 8 CTAs x 512 threads. 64 cols/CTA, W_hh
// slice register-resident, R7's conflict-free 16B k-interleave for LDS.
// h replicated in every CTA's SMEM, double-buffered (hbuf[2][512]); two
// 128-count mbarriers (slot 0/1).
// Producer (lane0 of each warp, holding its 4 cols via shfl-gather):
//   8x st.shared::cluster.v4 (one per CTA incl self) + 8x
//   mbarrier.arrive.release.cluster. Arrive is an atomic SYNCS op (the only
//   signal class that has ever worked on this part) and its issuing thread's
//   value is shfl-dependent on all 32 lanes' reads of the recycled slot ->
//   barrier-pass implies all prior-step reads returned (WAR-safe induction).
// Consumer: lane0 of each warp try_wait.parity.acquire.cluster on the LOCAL
//   barrier (16 waiters/CTA), __syncwarp, then conflict-free LDS compute.
// No L2 traffic, no __syncthreads in the loop; skew is bounded by the
// 128-arrival barrier itself.
__global__ void __launch_bounds__(512, 1) __cluster_dims__(8, 1, 1)
rnn_kernel(const float* __restrict__ W_hh, float* __restrict__ out) {
    __shared__ __align__(16) float hbuf[2][Hdim];
    __shared__ __align__(8) unsigned long long mbar[2];

    const int tid  = threadIdx.x;
    const int lane = tid & 31;
    const int warp = tid >> 5;
    unsigned rank;
    asm("mov.u32 %0, %%cluster_ctarank;" : "=r"(rank));
    const int batch = blockIdx.x >> 3;

    const int cg   = lane >> 3;          // column-subgroup within warp (0..3)
    const int sub  = lane & 7;           // position within 8-thread reduce group
    const int j    = (int)rank * 64 + warp * 4 + cg;  // this thread's column
    const int kb   = sub * 4;            // interleaved k-base (16B granule)

    // W_hh[k, j] for k = kb + 32*i + d (d=0..3) as 32 packed f32x2 pairs.
    unsigned long long w[32];
#pragma unroll
    for (int i = 0; i < 16; i++) {
        const int k = kb + 32 * i;
        w[2 * i]     = pk2(W_hh[(size_t)(k + 0) * Hdim + j], W_hh[(size_t)(k + 1) * Hdim + j]);
        w[2 * i + 1] = pk2(W_hh[(size_t)(k + 2) * Hdim + j], W_hh[(size_t)(k + 3) * Hdim + j]);
    }

    // zero both h buffers; init the two 128-arrival barriers
    for (int i = tid; i < 2 * Hdim; i += 512) (&hbuf[0][0])[i] = 0.f;
    const uint32_t lbuf = s2u(&hbuf[0][0]);
    const uint32_t lbar = s2u(&mbar[0]);
    if (tid == 0) {
        asm volatile("mbarrier.init.shared.b64 [%0], 128;" :: "r"(lbar) : "memory");
        asm volatile("mbarrier.init.shared.b64 [%0], 128;" :: "r"(lbar + 8) : "memory");
    }
    __syncthreads();
    // barriers + zeroed buffers visible cluster-wide before any remote op
    asm volatile("barrier.cluster.arrive.aligned;\n\tbarrier.cluster.wait.aligned;" ::: "memory");

    // mapa'd peer addresses (offsets preserved across CTAs)
    uint32_t rbuf[8], rbar[8];
#pragma unroll
    for (int r = 0; r < 8; r++) {
        asm("mapa.shared::cluster.u32 %0, %1, %2;" : "=r"(rbuf[r]) : "r"(lbuf), "r"(r));
        asm("mapa.shared::cluster.u32 %0, %1, %2;" : "=r"(rbar[r]) : "r"(lbar), "r"(r));
    }

    const int jw = (int)rank * 64 + warp * 4;          // lane0's 4-column base
    float* outw = out + (size_t)batch * Tdim * Hdim + jw;

    const bool leader = (sub == 0);                     // lanes 0,8,16,24
    const float* mycol = outw + cg;                     // leader's own column
    float pre_cur = leader ? ldcg_f1(mycol) : 0.f;      // pre for t=0

    uint32_t ph0 = 0, ph1 = 0;

    for (int t = 0; t < Tdim; ++t) {
        const int s = t & 1;

        if (t > 0) {
            // lane0 waits on the LOCAL slot barrier; warp joins via syncwarp.
            if (lane == 0) {
                const uint32_t par = s ? ph1 : ph0;
                asm volatile(
                    "{\n\t"
                    ".reg .pred P;\n\t"
                    "LW%=:\n\t"
                    "mbarrier.try_wait.parity.acquire.cluster.shared::cta.b64 P, [%0], %1, 0x989680;\n\t"
                    "@P bra LD%=;\n\t"
                    "bra LW%=;\n\t"
                    "LD%=:\n\t"
                    "}"
                    :: "r"(lbar + 8u * (uint32_t)s), "r"(par) : "memory");
            }
            __syncwarp();
            if (s) ph1 ^= 1; else ph0 ^= 1;
        }

        // ---- partial dot from local SMEM: 16 conflict-free LDS.128 ----
        unsigned long long a0 = 0ull, a1 = 0ull, a2 = 0ull, a3 = 0ull;
#pragma unroll
        for (int i = 0; i < 16; i += 2) {
            ulonglong2 ha = *(const ulonglong2*)(&hbuf[s][kb + 32 * i]);
            ulonglong2 hc = *(const ulonglong2*)(&hbuf[s][kb + 32 * (i + 1)]);
            fma2(a0, ha.x, w[2 * i]);
            fma2(a1, ha.y, w[2 * i + 1]);
            fma2(a2, hc.x, w[2 * i + 2]);
            fma2(a3, hc.y, w[2 * i + 3]);
        }

        // Prefetch next step's pre (independent of recurrence).
        float pre_next = 0.f;
        if (leader && (t + 1 < Tdim)) pre_next = ldcg_f1(mycol + (size_t)(t + 1) * Hdim);

        add2(a0, a1);
        add2(a2, a3);
        add2(a0, a2);
        float2 f0 = upk2(a0);
        float acc = f0.x + f0.y;
        acc += __shfl_xor_sync(0xffffffffu, acc, 4);
        acc += __shfl_xor_sync(0xffffffffu, acc, 2);
        acc += __shfl_xor_sync(0xffffffffu, acc, 1);

        // 4 leader lanes compute tanh in parallel.
        float hn = 0.f;
        if (leader) hn = tanhf(pre_cur + acc);

        // Gather leaders' results to lane 0 (3 independent shfls).
        float h1 = __shfl_sync(0xffffffffu, hn, 8);
        float h2 = __shfl_sync(0xffffffffu, hn, 16);
        float h3 = __shfl_sync(0xffffffffu, hn, 24);

        if (lane == 0) {
            if (t + 1 < Tdim) {
                const int s2 = (t + 1) & 1;
                const uint32_t off  = (uint32_t)(((s2 * Hdim) + jw) * 4);
                const uint32_t boff = 8u * (uint32_t)s2;
                // broadcast this warp's 4 columns to every CTA's buffer
#pragma unroll
                for (int r = 0; r < 8; r++) {
                    asm volatile("st.shared::cluster.v4.f32 [%0], {%1,%2,%3,%4};"
                                 :: "r"(rbuf[r] + off), "f"(hn), "f"(h1), "f"(h2), "f"(h3)
                                 : "memory");
                }
                // signal every CTA's slot barrier (release-cluster arrive)
#pragma unroll
                for (int r = 0; r < 8; r++) {
                    asm volatile("mbarrier.arrive.release.cluster.shared::cluster.b64 _, [%0];"
                                 :: "r"(rbar[r] + boff) : "memory");
                }
            }
            stcg_f4(outw + (size_t)t * Hdim, make_float4(hn, h1, h2, h3));  // output
        }
        if (leader) pre_cur = pre_next;
    }

    // trailing rendezvous: keep SMEM alive until all peers' remote ops land
    asm volatile("barrier.cluster.arrive.aligned;\n\tbarrier.cluster.wait.aligned;" ::: "memory");
}

// ---------------- launch ---------------------------------------------------
extern "C" void kernel_launch(void* const* d_in, const int* in_sizes, int n_in,
                              void* d_out, int out_size) {
    const float* x    = (const float*)d_in[0];  // [16, 2048, 512]
    const float* W_xh = (const float*)d_in[1];  // [512, 512]
    const float* W_hh = (const float*)d_in[2];  // [512, 512]
    const float* b    = (const float*)d_in[3];  // [512]
    // d_in[4] = A (DFA feedback) — backward-only, unused in forward.
    float* out = (float*)d_out;                 // [16, 2048, 512]

    dim3 ggrid((Bdim * Tdim) / GTM, Hdim / GTN);  // (256, 4)
    gemm_pre_kernel<<<ggrid, 256>>>(x, W_xh, b, out);

    // 16 batches x 8-CTA clusters = 128 CTAs.
    rnn_kernel<<<128, 512>>>(W_hh, out);
}

// round 15
// speedup vs baseline: 2.7180x; 2.7180x over previous
#include <cuda_runtime.h>
#include <cstdint>
#include <math.h>

#define Bdim 16
#define Tdim 2048
#define Ddim 512
#define Hdim 512

// ---------------- global staging state (no allocations allowed) ------------
__device__ float    g_h[2][Bdim][Hdim];      // double-buffered hidden state
__device__ unsigned g_flag[2][Bdim][8][8];   // [phase][batch][rank][pad 32B]
                                             // counter gets +64 per step (4 leader
                                             // reds x 16 warps per rank CTA)

// ---------------- helpers --------------------------------------------------
__device__ __forceinline__ unsigned long long pk2(float x, float y) {
    unsigned long long r;
    asm("mov.b64 %0, {%1,%2};" : "=l"(r) : "f"(x), "f"(y));
    return r;
}
__device__ __forceinline__ void fma2(unsigned long long& d, unsigned long long a, unsigned long long b) {
    asm("fma.rn.f32x2 %0, %1, %2, %0;" : "+l"(d) : "l"(a), "l"(b));
}
__device__ __forceinline__ void add2(unsigned long long& d, unsigned long long a) {
    asm("add.rn.f32x2 %0, %0, %1;" : "+l"(d) : "l"(a));
}
__device__ __forceinline__ float2 upk2(unsigned long long v) {
    float2 f;
    asm("mov.b64 {%0,%1}, %2;" : "=f"(f.x), "=f"(f.y) : "l"(v));
    return f;
}
__device__ __forceinline__ unsigned ldcg_u32(const unsigned* p) {
    unsigned v;
    asm volatile("ld.global.cg.u32 %0, [%1];" : "=r"(v) : "l"(p) : "memory");
    return v;
}
__device__ __forceinline__ float ldcg_f1(const float* p) {
    float v;
    asm volatile("ld.global.cg.f32 %0, [%1];" : "=f"(v) : "l"(p));
    return v;
}
__device__ __forceinline__ void stcg_f1(float* p, float v) {
    asm volatile("st.global.cg.f32 [%0], %1;" :: "l"(p), "f"(v) : "memory");
}
__device__ __forceinline__ ulonglong2 ldcg_u64x2(const void* p) {
    ulonglong2 v;
    asm volatile("ld.global.cg.v2.u64 {%0,%1}, [%2];"
                 : "=l"(v.x), "=l"(v.y) : "l"(p) : "memory");
    return v;
}
__device__ __forceinline__ void red_release_add(unsigned* p, unsigned v) {
    asm volatile("red.release.gpu.global.add.u32 [%0], %1;" :: "l"(p), "r"(v) : "memory");
}

// ---------------- Phase 1: pre = x @ W_xh + b  (fp32 SGEMM, f32x2) --------
// Writes straight into d_out (in-place pre buffer). Block (0,0) also zeroes
// the sync counters so graph replays stay deterministic.
#define GTM 128
#define GTN 128
#define GTK 16

__global__ void __launch_bounds__(256, 2)
gemm_pre_kernel(const float* __restrict__ X, const float* __restrict__ W,
                const float* __restrict__ bias, float* __restrict__ out) {
    if (blockIdx.x == 0 && blockIdx.y == 0) {
        unsigned* f = &g_flag[0][0][0][0];
        for (int i = threadIdx.x; i < 2 * Bdim * 8 * 8; i += 256) f[i] = 0u;
    }

    __shared__ __align__(16) float As[2][GTK][GTM];
    __shared__ __align__(16) float Bs[2][GTK][GTN];

    const int tid = threadIdx.x;
    const int mb = blockIdx.x * GTM;
    const int nb = blockIdx.y * GTN;
    const int K = Ddim, N = Hdim;

    unsigned long long acc[8][4];
#pragma unroll
    for (int i = 0; i < 8; i++)
#pragma unroll
        for (int q = 0; q < 4; q++) acc[i][q] = 0ull;

    const int tm = (tid >> 4) << 3;
    const int tn = (tid & 15) << 3;

    auto loadA = [&](int kt, int buf) {
#pragma unroll
        for (int i = 0; i < 2; i++) {
            int idx = tid + i * 256;
            int row = idx >> 2;
            int kq  = (idx & 3) << 2;
            float4 v = *(const float4*)(X + (size_t)(mb + row) * K + kt * GTK + kq);
            As[buf][kq + 0][row] = v.x;
            As[buf][kq + 1][row] = v.y;
            As[buf][kq + 2][row] = v.z;
            As[buf][kq + 3][row] = v.w;
        }
    };
    auto loadB = [&](int kt, int buf) {
#pragma unroll
        for (int i = 0; i < 2; i++) {
            int idx = tid + i * 256;
            int kk = idx >> 5;
            int nq = (idx & 31) << 2;
            *(float4*)(&Bs[buf][kk][nq]) =
                *(const float4*)(W + (size_t)(kt * GTK + kk) * N + nb + nq);
        }
    };

    loadA(0, 0);
    loadB(0, 0);
    __syncthreads();

    const int NT = K / GTK;
    for (int kt = 0; kt < NT; ++kt) {
        const int cur = kt & 1;
        if (kt + 1 < NT) {
            loadA(kt + 1, cur ^ 1);
            loadB(kt + 1, cur ^ 1);
        }
#pragma unroll
        for (int kk = 0; kk < GTK; ++kk) {
            float4 A0 = *(const float4*)(&As[cur][kk][tm]);
            float4 A1 = *(const float4*)(&As[cur][kk][tm + 4]);
            ulonglong2 B0 = *(const ulonglong2*)(&Bs[cur][kk][tn]);
            ulonglong2 B1 = *(const ulonglong2*)(&Bs[cur][kk][tn + 4]);
            float av[8] = {A0.x, A0.y, A0.z, A0.w, A1.x, A1.y, A1.z, A1.w};
#pragma unroll
            for (int mi = 0; mi < 8; ++mi) {
                unsigned long long ai = pk2(av[mi], av[mi]);
                fma2(acc[mi][0], ai, B0.x);
                fma2(acc[mi][1], ai, B0.y);
                fma2(acc[mi][2], ai, B1.x);
                fma2(acc[mi][3], ai, B1.y);
            }
        }
        __syncthreads();
    }

    unsigned long long bz[4];
#pragma unroll
    for (int q = 0; q < 4; q++)
        bz[q] = pk2(bias[nb + tn + 2 * q], bias[nb + tn + 2 * q + 1]);
#pragma unroll
    for (int mi = 0; mi < 8; ++mi) {
#pragma unroll
        for (int q = 0; q < 4; q++) {
            add2(acc[mi][q], bz[q]);
            *(unsigned long long*)(out + (size_t)(mb + tm + mi) * N + nb + tn + 2 * q) =
                acc[mi][q];
        }
    }
}

// ---------------- Phase 2: sequential tanh RNN (R9 skeleton, trimmed) ------
// 16 batches x 8 plain CTAs, 64 cols/CTA, W_hh slice in registers
// (16B-interleaved k: thread 'sub' owns k = 4*sub + 32*i + d — proven).
// Protocol (proven class: atomic red counters + full-join ballot + lockstep):
//   producer: each of the 4 LEADER lanes (sub==0) stores its OWN column
//     (st.cg.f32, lanes 0/8/16/24 -> one coalesced 16B transaction) and does
//     its OWN red.release.gpu (+1) -> counter gets +64/step per rank; each
//     red orders that leader's data store, and each leader's value is
//     shfl-dependent on its 8-lane group's reads (4 groups cover the warp),
//     so counter-full still implies all old-slot reads completed (WAR-safe).
//     No gather shfls, no single-lane store serialization.
//   consumer: all warps; lane polls counter[lane&7] with a 2-DEEP pipelined
//     loop (two loads in flight -> ~half detect quantization), full ballot.
//   per-step __syncthreads keeps CTA warps lockstep (required for rank-
//   aggregated counters; proven R4/7/9).
__global__ void __launch_bounds__(512, 1)
rnn_kernel(const float* __restrict__ W_hh, float* __restrict__ out) {
    const int tid  = threadIdx.x;
    const int lane = tid & 31;
    const int warp = tid >> 5;
    const int rank  = blockIdx.x & 7;
    const int batch = blockIdx.x >> 3;

    const int cg   = lane >> 3;          // column-subgroup within warp (0..3)
    const int sub  = lane & 7;           // position within 8-thread reduce group
    const int j    = rank * 64 + warp * 4 + cg;  // this thread's column
    const int kb   = sub * 4;            // interleaved k-base (16B granule)

    // W_hh[k, j] for k = kb + 32*i + d (d=0..3) as 32 packed f32x2 pairs.
    unsigned long long w[32];
#pragma unroll
    for (int i = 0; i < 16; i++) {
        const int k = kb + 32 * i;
        w[2 * i]     = pk2(W_hh[(size_t)(k + 0) * Hdim + j], W_hh[(size_t)(k + 1) * Hdim + j]);
        w[2 * i + 1] = pk2(W_hh[(size_t)(k + 2) * Hdim + j], W_hh[(size_t)(k + 3) * Hdim + j]);
    }

    float* outc = out + (size_t)batch * Tdim * Hdim + j;   // this thread's column
    const bool leader = (sub == 0);                        // lanes 0,8,16,24
    float pre_cur = leader ? ldcg_f1(outc) : 0.f;          // pre for t=0

    const unsigned* pollp[2] = { &g_flag[0][batch][lane & 7][0],
                                 &g_flag[1][batch][lane & 7][0] };
    unsigned* redp[2] = { &g_flag[0][batch][rank][0], &g_flag[1][batch][rank][0] };
    const unsigned long long* hbase[2] = {
        (const unsigned long long*)&g_h[0][batch][0],
        (const unsigned long long*)&g_h[1][batch][0] };

    for (int t = 0; t < Tdim; ++t) {
        const int p = t & 1;

        // Prefetch next step's pre BEFORE the poll (hides under the spin).
        float pre_next = 0.f;
        if (leader && (t + 1 < Tdim)) pre_next = ldcg_f1(outc + (size_t)(t + 1) * Hdim);

        unsigned long long a0 = 0ull, a1 = 0ull, a2 = 0ull, a3 = 0ull;
        if (t > 0) {
            // ---- 2-deep pipelined full-join poll of the 8 rank counters ----
            const unsigned tgt = 64u * (unsigned)((t + 1) >> 1);
            const unsigned* fp = pollp[p];
            unsigned va = ldcg_u32(fp);
            for (;;) {
                unsigned vb = ldcg_u32(fp);          // keep 2nd load in flight
                if (__all_sync(0xffffffffu, va >= tgt)) break;
                va = ldcg_u32(fp);
                if (__all_sync(0xffffffffu, vb >= tgt)) break;
            }

            // ---- direct L2 loads of interleaved chunks + 4 fma chains ----
            const unsigned long long* hb = hbase[p];
#pragma unroll
            for (int i = 0; i < 16; i += 2) {
                ulonglong2 ha = ldcg_u64x2(hb + (kb + 32 * i) / 2);
                ulonglong2 hc = ldcg_u64x2(hb + (kb + 32 * (i + 1)) / 2);
                fma2(a0, ha.x, w[2 * i]);
                fma2(a1, ha.y, w[2 * i + 1]);
                fma2(a2, hc.x, w[2 * i + 2]);
                fma2(a3, hc.y, w[2 * i + 3]);
            }
        }

        add2(a0, a1);
        add2(a2, a3);
        add2(a0, a2);
        float2 f0 = upk2(a0);
        float acc = f0.x + f0.y;
        acc += __shfl_xor_sync(0xffffffffu, acc, 4);
        acc += __shfl_xor_sync(0xffffffffu, acc, 2);
        acc += __shfl_xor_sync(0xffffffffu, acc, 1);

        // 4 leader lanes: tanh in parallel, store OWN column, red OWN signal.
        if (leader) {
            float hn = tanhf(pre_cur + acc);
            if (t + 1 < Tdim) {
                stcg_f1(&g_h[p ^ 1][batch][j], hn);        // publish (coalesced 16B)
                red_release_add(redp[p ^ 1], 1u);          // orders MY store
            }
            stcg_f1(outc + (size_t)t * Hdim, hn);          // final output
            pre_cur = pre_next;
        }

        __syncthreads();  // lockstep (required for rank-aggregated counters)
    }
}

// ---------------- launch ---------------------------------------------------
extern "C" void kernel_launch(void* const* d_in, const int* in_sizes, int n_in,
                              void* d_out, int out_size) {
    const float* x    = (const float*)d_in[0];  // [16, 2048, 512]
    const float* W_xh = (const float*)d_in[1];  // [512, 512]
    const float* W_hh = (const float*)d_in[2];  // [512, 512]
    const float* b    = (const float*)d_in[3];  // [512]
    // d_in[4] = A (DFA feedback) — backward-only, unused in forward.
    float* out = (float*)d_out;                 // [16, 2048, 512]

    dim3 ggrid((Bdim * Tdim) / GTM, Hdim / GTN);  // (256, 4)
    gemm_pre_kernel<<<ggrid, 256>>>(x, W_xh, b, out);

    rnn_kernel<<<128, 512>>>(W_hh, out);  // 16 batches x 8 CTAs
}